// round 15
// baseline (speedup 1.0000x reference)
#include <cuda_runtime.h>

#define NB 524288
#define T_OBS 8
#define T_PRE 12
#define HH 8
#define EE 16

typedef unsigned long long ull;

// Duplicated (w,w) packed weights.
// Gates i,f,o pre-scaled by 0.5 (sigmoid(x)=0.5*tanh(x/2)+0.5); gate g unscaled.
struct __align__(16) Wpack {
    float2 W[2][8][8][4];   // [phase][u][k][gate]
    float2 A[2][8][2][4];   // [phase][u][m][gate]   (A = W_ih @ W_in, folded)
    float2 Bz[2][8][4];     // [phase][u][gate]      (b_ih + b_hh + W_ih@b_in, folded)
};
__device__ Wpack gPack;

// ---------------- prep: fold embedding into gate weights, scale, duplicate ----------------
__global__ void prep_kernel(
    const float* __restrict__ W_in, const float* __restrict__ b_in,
    const float* __restrict__ Wih_o, const float* __restrict__ Whh_o,
    const float* __restrict__ bih_o, const float* __restrict__ bhh_o,
    const float* __restrict__ Wih_p, const float* __restrict__ Whh_p,
    const float* __restrict__ bih_p, const float* __restrict__ bhh_p)
{
    int t = threadIdx.x;
    if (t >= 64) return;
    int ph = t >> 5, r = t & 31;
    const float* Wih = ph ? Wih_p : Wih_o;
    const float* Whh = ph ? Whh_p : Whh_o;
    const float* bih = ph ? bih_p : bih_o;
    const float* bhh = ph ? bhh_p : bhh_o;
    int g = r >> 3, j = r & 7;                       // rows: i(0-7) f(8-15) g(16-23) o(24-31)
    float sc = (g == 2) ? 1.0f : 0.5f;               // sigmoid via tanh(x/2); g: tanh direct
    float a0 = 0.f, a1 = 0.f, bb = bih[r] + bhh[r];
    for (int e = 0; e < EE; e++) {
        float w = Wih[r * EE + e];
        a0 += w * W_in[e * 2 + 0];
        a1 += w * W_in[e * 2 + 1];
        bb += w * b_in[e];
    }
    a0 *= sc; a1 *= sc; bb *= sc;
    gPack.A[ph][j][0][g] = make_float2(a0, a0);
    gPack.A[ph][j][1][g] = make_float2(a1, a1);
    gPack.Bz[ph][j][g]   = make_float2(bb, bb);
    for (int k = 0; k < HH; k++) {
        float w = Whh[r * HH + k] * sc;
        gPack.W[ph][j][k][g] = make_float2(w, w);
    }
}

// ---------------- packed f32x2 helpers ----------------
__device__ __forceinline__ ull fma2(ull a, ull b, ull c) {
    ull d; asm("fma.rn.f32x2 %0, %1, %2, %3;" : "=l"(d) : "l"(a), "l"(b), "l"(c)); return d;
}
__device__ __forceinline__ ull mul2(ull a, ull b) {
    ull d; asm("mul.rn.f32x2 %0, %1, %2;" : "=l"(d) : "l"(a), "l"(b)); return d;
}
__device__ __forceinline__ ull add2(ull a, ull b) {
    ull d; asm("add.rn.f32x2 %0, %1, %2;" : "=l"(d) : "l"(a), "l"(b)); return d;
}
__device__ __forceinline__ ull pk(float lo, float hi) {
    ull d; asm("mov.b64 %0, {%1, %2};" : "=l"(d) : "f"(lo), "f"(hi)); return d;
}
__device__ __forceinline__ void unpk(ull v, float& lo, float& hi) {
    asm("mov.b64 {%0, %1}, %2;" : "=f"(lo), "=f"(hi) : "l"(v));
}
__device__ __forceinline__ float tanhap(float x) {
    float y; asm("tanh.approx.f32 %0, %1;" : "=f"(y) : "f"(x)); return y;
}
__device__ __forceinline__ void cp16(unsigned dst, const void* src) {
    asm volatile("cp.async.cg.shared.global [%0], [%1], 16;" :: "r"(dst), "l"(src) : "memory");
}
__device__ __forceinline__ void cp_commit() {
    asm volatile("cp.async.commit_group;" ::: "memory");
}
__device__ __forceinline__ void cp_wait1() {
    asm volatile("cp.async.wait_group 1;" ::: "memory");
}

// LSTM epilogue, scalar per lane. acc = [i/2, f/2, g, o/2] preactivations (packed).
__device__ __forceinline__ void lstm_unit(const ull acc[4], float& cl, float& ch, ull& hout)
{
    float il, ih, fl, fh, gl, gh, ol, oh;
    unpk(acc[0], il, ih);
    unpk(acc[1], fl, fh);
    unpk(acc[2], gl, gh);
    unpk(acc[3], ol, oh);
    float til = tanhap(il), tih = tanhap(ih);
    float tfl = tanhap(fl), tfh = tanhap(fh);
    float tgl = tanhap(gl), tgh = tanhap(gh);
    float tol = tanhap(ol), toh = tanhap(oh);
    float sil = fmaf(til, 0.5f, 0.5f), sih = fmaf(tih, 0.5f, 0.5f);
    float sfl = fmaf(tfl, 0.5f, 0.5f), sfh = fmaf(tfh, 0.5f, 0.5f);
    float sol = fmaf(tol, 0.5f, 0.5f), soh = fmaf(toh, 0.5f, 0.5f);
    cl = fmaf(sfl, cl, sil * tgl);
    ch = fmaf(sfh, ch, sih * tgh);
    float tcl = tanhap(cl), tch = tanhap(ch);
    hout = pk(sol * tcl, soh * tch);
}

// Recurrent MAC for one pair: acc += W^T h, register weights; 2 tree halves
__device__ __forceinline__ void rec_mac(ull acc[4], const ull Wr[8][4], const ull* hv)
{
    ulonglong2 h01 = *(const ulonglong2*)(hv + 0);
    ulonglong2 h23 = *(const ulonglong2*)(hv + 2);
    ulonglong2 h45 = *(const ulonglong2*)(hv + 4);
    ulonglong2 h67 = *(const ulonglong2*)(hv + 6);
    #pragma unroll
    for (int g = 0; g < 4; g++) {
        ull a = fma2(Wr[0][g], h01.x, acc[g]);
        a = fma2(Wr[1][g], h01.y, a);
        a = fma2(Wr[2][g], h23.x, a);
        a = fma2(Wr[3][g], h23.y, a);
        ull b = mul2(Wr[4][g], h45.x);
        b = fma2(Wr[5][g], h45.y, b);
        b = fma2(Wr[6][g], h67.x, b);
        b = fma2(Wr[7][g], h67.y, b);
        acc[g] = add2(a, b);
    }
}

// hw: this warp's h-exchange region (2 bufs x 8 pairs x 8 units = 128 ull)
// xs: this warp's x-staging region (4 slots x 8 pairs x float4)
// cf: this unit's coefficient row in smem: [A0(2), A1(2), Bz(2)] as ulonglong2
template<int TSTEPS, int PH>
__device__ __forceinline__ void run_phase(ull* hw, float4* xs, const ulonglong2* cf,
    const float* __restrict__ xbase, int P0, int q, int u,
    ull& hp0, ull& hp1,
    float& c0l, float& c0h, float& c1l, float& c1h)
{
    // ---- phase-resident recurrent weights in registers (from global, once) ----
    ull Wr[8][4];
    #pragma unroll
    for (int k = 0; k < 8; k++) {
        const ulonglong2* ww = (const ulonglong2*)&gPack.W[PH][u][k][0];
        ulonglong2 q01 = __ldg(ww), q23 = __ldg(ww + 1);
        Wr[k][0] = q01.x; Wr[k][1] = q01.y; Wr[k][2] = q23.x; Wr[k][3] = q23.y;
    }

    const float4* gx = (const float4*)xbase;   // x[t] for pair P: gx[t*S4 + P]
    const size_t S4 = (size_t)NB / 2;
    const unsigned xs_u32 = (unsigned)__cvta_generic_to_shared(xs);

    __syncwarp();   // prior readers of xs (previous phase) are done

    // prefill slots 0,1 (t=0,1); only lane u==0 of each pair group copies
    if (u == 0) {
        cp16(xs_u32 + (unsigned)((0 * 8 + q) * 16),     gx + P0);
        cp16(xs_u32 + (unsigned)((0 * 8 + q + 4) * 16), gx + P0 + 4);
    }
    cp_commit();
    if (u == 0) {
        cp16(xs_u32 + (unsigned)((1 * 8 + q) * 16),     gx + S4 + P0);
        cp16(xs_u32 + (unsigned)((1 * 8 + q + 4) * 16), gx + S4 + P0 + 4);
    }
    cp_commit();

    // publish initial h into buffer 0 (ordered by the syncwarp at loop top)
    hw[(q << 3) + u] = hp0;
    hw[((q + 4) << 3) + u] = hp1;

    #pragma unroll 4
    for (int t = 0; t < TSTEPS; t++) {
        cp_wait1();          // lane u==0: slot t&3 landed; others: no-op
        __syncwarp();        // make lane0's cp.async data + last step's STS visible

        float4 xA = xs[(t & 3) * 8 + q];
        float4 xB = xs[(t & 3) * 8 + q + 4];

        // coefficients from smem (broadcast LDS; re-loaded per step so ptxas
        // rematerializes instead of spilling under the 128-reg cap)
        ulonglong2 cA0a = cf[0], cA0b = cf[1];   // A0[0..3]
        ulonglong2 cA1a = cf[2], cA1b = cf[3];   // A1[0..3]
        ulonglong2 cBza = cf[4], cBzb = cf[5];   // Bz[0..3]

        // issue prefetch for t+2 (distance 2)
        if (t + 2 < TSTEPS) {
            if (u == 0) {
                const float4* src = gx + (size_t)(t + 2) * S4;
                cp16(xs_u32 + (unsigned)((((t + 2) & 3) * 8 + q) * 16),     src + P0);
                cp16(xs_u32 + (unsigned)((((t + 2) & 3) * 8 + q + 4) * 16), src + P0 + 4);
            }
        }
        cp_commit();         // uniform group counting

        const ull* hb = hw + ((t & 1) << 6);

        // ---- pair 0 ----
        {
            ull px0 = pk(xA.x, xA.z), px1 = pk(xA.y, xA.w);
            ull acc[4];
            acc[0] = fma2(cA0a.x, px0, cBza.x); acc[0] = fma2(cA1a.x, px1, acc[0]);
            acc[1] = fma2(cA0a.y, px0, cBza.y); acc[1] = fma2(cA1a.y, px1, acc[1]);
            acc[2] = fma2(cA0b.x, px0, cBzb.x); acc[2] = fma2(cA1b.x, px1, acc[2]);
            acc[3] = fma2(cA0b.y, px0, cBzb.y); acc[3] = fma2(cA1b.y, px1, acc[3]);
            rec_mac(acc, Wr, hb + (q << 3));
            lstm_unit(acc, c0l, c0h, hp0);
        }
        // ---- pair 1 ----
        {
            ull py0 = pk(xB.x, xB.z), py1 = pk(xB.y, xB.w);
            ull acc[4];
            acc[0] = fma2(cA0a.x, py0, cBza.x); acc[0] = fma2(cA1a.x, py1, acc[0]);
            acc[1] = fma2(cA0a.y, py0, cBza.y); acc[1] = fma2(cA1a.y, py1, acc[1]);
            acc[2] = fma2(cA0b.x, py0, cBzb.x); acc[2] = fma2(cA1b.x, py1, acc[2]);
            acc[3] = fma2(cA0b.y, py0, cBzb.y); acc[3] = fma2(cA1b.y, py1, acc[3]);
            rec_mac(acc, Wr, hb + ((q + 4) << 3));
            lstm_unit(acc, c1l, c1h, hp1);
        }

        if (t + 1 < TSTEPS) {
            ull* hn = hw + (((t + 1) & 1) << 6);
            hn[(q << 3) + u] = hp0;
            hn[((q + 4) << 3) + u] = hp1;
            // visibility handled by the syncwarp at the top of the next step
        }
    }
}

__global__ void __launch_bounds__(128, 4)
enc_kernel(const float* __restrict__ obs, const float* __restrict__ pre,
           const float* __restrict__ h0, const float* __restrict__ c0,
           const float* __restrict__ c0p, float* __restrict__ out)
{
    __shared__ ull hbuf[4][128];             // per-warp: 2 bufs x 8 pairs x 8 units
    __shared__ float4 xbuf[4][4][8];         // per-warp: 4 slots x 8 pairs
    __shared__ ulonglong2 sCoef[2][8][6];    // [phase][unit][A0(2) A1(2) Bz(2)]

    // load coefficient table once per block
    {
        int i = threadIdx.x;
        if (i < 96) {
            int ph = i / 48, rem = i % 48, uu = rem / 6, e = rem % 6;
            const ulonglong2* src;
            if (e < 2)      src = (const ulonglong2*)&gPack.A[ph][uu][0][0] + e;
            else if (e < 4) src = (const ulonglong2*)&gPack.A[ph][uu][1][0] + (e - 2);
            else            src = (const ulonglong2*)&gPack.Bz[ph][uu][0] + (e - 4);
            sCoef[ph][uu][e] = __ldg(src);
        }
    }
    __syncthreads();

    // warp = 8 pairs = 16 elements; lane = q*8 + u; lane handles pairs q and q+4
    const int lane = threadIdx.x & 31;
    const int warp = threadIdx.x >> 5;
    const int q = lane >> 3;                 // pair-slot (0..3)
    const int u = lane & 7;                  // hidden unit (0..7)
    const int gw = blockIdx.x * 4 + warp;    // global warp index
    const int P0 = gw * 8 + q;               // first pair
    const int P1 = P0 + 4;                   // second pair
    const int e0 = 2 * P0, e1 = 2 * P1;

    // initial state: [B,8] layout, stride 8
    ull hp0 = pk(h0[(size_t)e0 * 8 + u], h0[(size_t)(e0 + 1) * 8 + u]);
    ull hp1 = pk(h0[(size_t)e1 * 8 + u], h0[(size_t)(e1 + 1) * 8 + u]);
    float c0l = c0[(size_t)e0 * 8 + u], c0h = c0[(size_t)(e0 + 1) * 8 + u];
    float c1l = c0[(size_t)e1 * 8 + u], c1h = c0[(size_t)(e1 + 1) * 8 + u];

    run_phase<T_OBS, 0>(hbuf[warp], &xbuf[warp][0][0], &sCoef[0][u][0], obs, P0, q, u,
                        hp0, hp1, c0l, c0h, c1l, c1h);
    // c_out = transpose(h_obs): out[u*B + b]
    *(ull*)(out + (size_t)u * NB + e0) = hp0;
    *(ull*)(out + (size_t)u * NB + e1) = hp1;

    c0l = c0p[(size_t)e0 * 8 + u]; c0h = c0p[(size_t)(e0 + 1) * 8 + u];  // cell re-init
    c1l = c0p[(size_t)e1 * 8 + u]; c1h = c0p[(size_t)(e1 + 1) * 8 + u];
    run_phase<T_PRE, 1>(hbuf[warp], &xbuf[warp][0][0], &sCoef[1][u][0], pre, P0, q, u,
                        hp0, hp1, c0l, c0h, c1l, c1h);
    float* out2 = out + (size_t)NB * 8;
    *(ull*)(out2 + (size_t)u * NB + e0) = hp0;
    *(ull*)(out2 + (size_t)u * NB + e1) = hp1;
}

extern "C" void kernel_launch(void* const* d_in, const int* in_sizes, int n_in,
                              void* d_out, int out_size)
{
    const float* obs   = (const float*)d_in[0];
    const float* pre   = (const float*)d_in[1];
    const float* h0    = (const float*)d_in[2];
    const float* c0    = (const float*)d_in[3];
    const float* c0p   = (const float*)d_in[4];
    const float* W_in  = (const float*)d_in[5];
    const float* b_in  = (const float*)d_in[6];
    const float* Wih_o = (const float*)d_in[7];
    const float* Whh_o = (const float*)d_in[8];
    const float* bih_o = (const float*)d_in[9];
    const float* bhh_o = (const float*)d_in[10];
    const float* Wih_p = (const float*)d_in[11];
    const float* Whh_p = (const float*)d_in[12];
    const float* bih_p = (const float*)d_in[13];
    const float* bhh_p = (const float*)d_in[14];

    prep_kernel<<<1, 64>>>(W_in, b_in, Wih_o, Whh_o, bih_o, bhh_o,
                           Wih_p, Whh_p, bih_p, bhh_p);
    // 1 warp = 16 elems, 4 warps/block -> 64 elems/block
    enc_kernel<<<NB / 64, 128>>>(obs, pre, h0, c0, c0p, (float*)d_out);
}

// round 16
// speedup vs baseline: 1.1399x; 1.1399x over previous
#include <cuda_runtime.h>

#define NB 524288
#define T_OBS 8
#define T_PRE 12
#define HH 8
#define EE 16

typedef unsigned long long ull;

// Duplicated (w,w) packed weights.
// Gates i,f,o pre-scaled by 0.5 (sigmoid(x)=0.5*tanh(x/2)+0.5); gate g unscaled.
struct __align__(16) Wpack {
    float2 W[2][8][8][4];   // [phase][u][k][gate]
    float2 A[2][8][2][4];   // [phase][u][m][gate]   (A = W_ih @ W_in, folded)
    float2 Bz[2][8][4];     // [phase][u][gate]      (b_ih + b_hh + W_ih@b_in, folded)
};
__device__ Wpack gPack;

// ---------------- prep: fold embedding into gate weights, scale, duplicate ----------------
__global__ void prep_kernel(
    const float* __restrict__ W_in, const float* __restrict__ b_in,
    const float* __restrict__ Wih_o, const float* __restrict__ Whh_o,
    const float* __restrict__ bih_o, const float* __restrict__ bhh_o,
    const float* __restrict__ Wih_p, const float* __restrict__ Whh_p,
    const float* __restrict__ bih_p, const float* __restrict__ bhh_p)
{
    int t = threadIdx.x;
    if (t >= 64) return;
    int ph = t >> 5, r = t & 31;
    const float* Wih = ph ? Wih_p : Wih_o;
    const float* Whh = ph ? Whh_p : Whh_o;
    const float* bih = ph ? bih_p : bih_o;
    const float* bhh = ph ? bhh_p : bhh_o;
    int g = r >> 3, j = r & 7;                       // rows: i(0-7) f(8-15) g(16-23) o(24-31)
    float sc = (g == 2) ? 1.0f : 0.5f;               // sigmoid via tanh(x/2); g: tanh direct
    float a0 = 0.f, a1 = 0.f, bb = bih[r] + bhh[r];
    for (int e = 0; e < EE; e++) {
        float w = Wih[r * EE + e];
        a0 += w * W_in[e * 2 + 0];
        a1 += w * W_in[e * 2 + 1];
        bb += w * b_in[e];
    }
    a0 *= sc; a1 *= sc; bb *= sc;
    gPack.A[ph][j][0][g] = make_float2(a0, a0);
    gPack.A[ph][j][1][g] = make_float2(a1, a1);
    gPack.Bz[ph][j][g]   = make_float2(bb, bb);
    for (int k = 0; k < HH; k++) {
        float w = Whh[r * HH + k] * sc;
        gPack.W[ph][j][k][g] = make_float2(w, w);
    }
}

// ---------------- packed f32x2 helpers ----------------
__device__ __forceinline__ ull fma2(ull a, ull b, ull c) {
    ull d; asm("fma.rn.f32x2 %0, %1, %2, %3;" : "=l"(d) : "l"(a), "l"(b), "l"(c)); return d;
}
__device__ __forceinline__ ull mul2(ull a, ull b) {
    ull d; asm("mul.rn.f32x2 %0, %1, %2;" : "=l"(d) : "l"(a), "l"(b)); return d;
}
__device__ __forceinline__ ull add2(ull a, ull b) {
    ull d; asm("add.rn.f32x2 %0, %1, %2;" : "=l"(d) : "l"(a), "l"(b)); return d;
}
__device__ __forceinline__ ull pk(float lo, float hi) {
    ull d; asm("mov.b64 %0, {%1, %2};" : "=l"(d) : "f"(lo), "f"(hi)); return d;
}
__device__ __forceinline__ void unpk(ull v, float& lo, float& hi) {
    asm("mov.b64 {%0, %1}, %2;" : "=f"(lo), "=f"(hi) : "l"(v));
}
__device__ __forceinline__ float tanhap(float x) {
    float y; asm("tanh.approx.f32 %0, %1;" : "=f"(y) : "f"(x)); return y;
}
__device__ __forceinline__ void cp16(unsigned dst, const void* src) {
    asm volatile("cp.async.cg.shared.global [%0], [%1], 16;" :: "r"(dst), "l"(src) : "memory");
}
__device__ __forceinline__ void cp_commit() {
    asm volatile("cp.async.commit_group;" ::: "memory");
}
__device__ __forceinline__ void cp_wait1() {
    asm volatile("cp.async.wait_group 1;" ::: "memory");
}

// LSTM epilogue, scalar per lane. acc = [i/2, f/2, g, o/2] preactivations (packed).
__device__ __forceinline__ void lstm_unit(const ull acc[4], float& cl, float& ch, ull& hout)
{
    float il, ih, fl, fh, gl, gh, ol, oh;
    unpk(acc[0], il, ih);
    unpk(acc[1], fl, fh);
    unpk(acc[2], gl, gh);
    unpk(acc[3], ol, oh);
    float til = tanhap(il), tih = tanhap(ih);
    float tfl = tanhap(fl), tfh = tanhap(fh);
    float tgl = tanhap(gl), tgh = tanhap(gh);
    float tol = tanhap(ol), toh = tanhap(oh);
    float sil = fmaf(til, 0.5f, 0.5f), sih = fmaf(tih, 0.5f, 0.5f);
    float sfl = fmaf(tfl, 0.5f, 0.5f), sfh = fmaf(tfh, 0.5f, 0.5f);
    float sol = fmaf(tol, 0.5f, 0.5f), soh = fmaf(toh, 0.5f, 0.5f);
    cl = fmaf(sfl, cl, sil * tgl);
    ch = fmaf(sfh, ch, sih * tgh);
    float tcl = tanhap(cl), tch = tanhap(ch);
    hout = pk(sol * tcl, soh * tch);
}

// Recurrent MAC for one pair: acc += W^T h, register weights; 2 tree halves
__device__ __forceinline__ void rec_mac(ull acc[4], const ull Wr[8][4], const ull* hv)
{
    ulonglong2 h01 = *(const ulonglong2*)(hv + 0);
    ulonglong2 h23 = *(const ulonglong2*)(hv + 2);
    ulonglong2 h45 = *(const ulonglong2*)(hv + 4);
    ulonglong2 h67 = *(const ulonglong2*)(hv + 6);
    #pragma unroll
    for (int g = 0; g < 4; g++) {
        ull a = fma2(Wr[0][g], h01.x, acc[g]);
        a = fma2(Wr[1][g], h01.y, a);
        a = fma2(Wr[2][g], h23.x, a);
        a = fma2(Wr[3][g], h23.y, a);
        ull b = mul2(Wr[4][g], h45.x);
        b = fma2(Wr[5][g], h45.y, b);
        b = fma2(Wr[6][g], h67.x, b);
        b = fma2(Wr[7][g], h67.y, b);
        acc[g] = add2(a, b);
    }
}

// h-exchange layout: pair stride = 10 ull (80B, 16B-aligned).
// Offsets 0/80/160/240B hit disjoint bank groups -> conflict-free LDS.128.
#define HSTRIDE 10
#define HBUF    80      // ull per buffer (8 pair-slots x 10)

// hw: this warp's h-exchange region (2 bufs x HBUF ull)
// xs: this warp's x-staging region (4 slots x 8 pairs x float4)
template<int TSTEPS, int PH>
__device__ __forceinline__ void run_phase(ull* hw, float4* xs,
    const float* __restrict__ xbase, int P0, int q, int u,
    ull& hp0, ull& hp1,
    float& c0l, float& c0h, float& c1l, float& c1h)
{
    // ---- phase-resident coefficients in registers (from global, once) ----
    ull Wr[8][4];
    #pragma unroll
    for (int k = 0; k < 8; k++) {
        const ulonglong2* ww = (const ulonglong2*)&gPack.W[PH][u][k][0];
        ulonglong2 q01 = __ldg(ww), q23 = __ldg(ww + 1);
        Wr[k][0] = q01.x; Wr[k][1] = q01.y; Wr[k][2] = q23.x; Wr[k][3] = q23.y;
    }
    ull A0[4], A1[4], Bz[4];
    {
        const ulonglong2* a0 = (const ulonglong2*)&gPack.A[PH][u][0][0];
        const ulonglong2* a1 = (const ulonglong2*)&gPack.A[PH][u][1][0];
        const ulonglong2* bz = (const ulonglong2*)&gPack.Bz[PH][u][0];
        ulonglong2 w01 = __ldg(a0), w23 = __ldg(a0 + 1);
        ulonglong2 v01 = __ldg(a1), v23 = __ldg(a1 + 1);
        ulonglong2 b01 = __ldg(bz), b23 = __ldg(bz + 1);
        A0[0] = w01.x; A0[1] = w01.y; A0[2] = w23.x; A0[3] = w23.y;
        A1[0] = v01.x; A1[1] = v01.y; A1[2] = v23.x; A1[3] = v23.y;
        Bz[0] = b01.x; Bz[1] = b01.y; Bz[2] = b23.x; Bz[3] = b23.y;
    }

    const float4* gx = (const float4*)xbase;   // x[t] for pair P: gx[t*S4 + P]
    const size_t S4 = (size_t)NB / 2;
    const unsigned xs_u32 = (unsigned)__cvta_generic_to_shared(xs);

    // lane's cp.async role: lanes u==0 and u==4 each copy one pair's 16B
    // -> ONE LDGSTS warp-instruction per slot (8 active lanes)
    const bool cp_lane = (u & 3) == 0;
    const int cp_slot  = q + (u & 4);            // pair-slot this lane copies (0..7)
    const int cp_P     = P0 - q + cp_slot;       // global pair idx (P0-q = gw*8)

    __syncwarp();   // prior readers of xs (previous phase) are done

    // prefill slots 0,1 (t=0,1)
    if (cp_lane) cp16(xs_u32 + (unsigned)((0 * 8 + cp_slot) * 16), gx + cp_P);
    cp_commit();
    if (cp_lane) cp16(xs_u32 + (unsigned)((1 * 8 + cp_slot) * 16), gx + S4 + cp_P);
    cp_commit();

    // publish initial h into buffer 0 (ordered by the syncwarp at loop top)
    hw[q * HSTRIDE + u] = hp0;
    hw[(q + 4) * HSTRIDE + u] = hp1;

    #pragma unroll 4
    for (int t = 0; t < TSTEPS; t++) {
        cp_wait1();          // slot t&3 landed (cp lanes); others: no-op
        __syncwarp();        // make cp.async data + last step's STS visible

        float4 xA = xs[(t & 3) * 8 + q];
        float4 xB = xs[(t & 3) * 8 + q + 4];

        ull acc0[4], acc1[4];
        {
            ull px0 = pk(xA.x, xA.z), px1 = pk(xA.y, xA.w);
            ull py0 = pk(xB.x, xB.z), py1 = pk(xB.y, xB.w);
            #pragma unroll
            for (int g = 0; g < 4; g++) {
                acc0[g] = fma2(A0[g], px0, Bz[g]); acc0[g] = fma2(A1[g], px1, acc0[g]);
                acc1[g] = fma2(A0[g], py0, Bz[g]); acc1[g] = fma2(A1[g], py1, acc1[g]);
            }
        }

        // issue prefetch for t+2 (distance 2) — one LDGSTS warp-instruction
        if (t + 2 < TSTEPS) {
            if (cp_lane) {
                const float4* src = gx + (size_t)(t + 2) * S4;
                cp16(xs_u32 + (unsigned)((((t + 2) & 3) * 8 + cp_slot) * 16), src + cp_P);
            }
        }
        cp_commit();         // uniform group counting

        const ull* hb = hw + (t & 1) * HBUF;
        rec_mac(acc0, Wr, hb + q * HSTRIDE);
        rec_mac(acc1, Wr, hb + (q + 4) * HSTRIDE);

        ull* hn = hw + ((t + 1) & 1) * HBUF;
        lstm_unit(acc0, c0l, c0h, hp0);
        if (t + 1 < TSTEPS) hn[q * HSTRIDE + u] = hp0;        // early STS pair 0
        lstm_unit(acc1, c1l, c1h, hp1);
        if (t + 1 < TSTEPS) hn[(q + 4) * HSTRIDE + u] = hp1;  // early STS pair 1
        // visibility handled by the syncwarp at the top of the next step
    }
}

__global__ void __launch_bounds__(128, 3)
enc_kernel(const float* __restrict__ obs, const float* __restrict__ pre,
           const float* __restrict__ h0, const float* __restrict__ c0,
           const float* __restrict__ c0p, float* __restrict__ out)
{
    __shared__ ull hbuf[4][2 * HBUF];        // per-warp: 2 bufs x 8 pairs x stride10
    __shared__ float4 xbuf[4][4][8];         // per-warp: 4 slots x 8 pairs

    // warp = 8 pairs = 16 elements; lane = q*8 + u; lane handles pairs q and q+4
    const int lane = threadIdx.x & 31;
    const int warp = threadIdx.x >> 5;
    const int q = lane >> 3;                 // pair-slot (0..3)
    const int u = lane & 7;                  // hidden unit (0..7)
    const int gw = blockIdx.x * 4 + warp;    // global warp index
    const int P0 = gw * 8 + q;               // first pair
    const int P1 = P0 + 4;                   // second pair
    const int e0 = 2 * P0, e1 = 2 * P1;

    // initial state: [B,8] layout, stride 8
    ull hp0 = pk(h0[(size_t)e0 * 8 + u], h0[(size_t)(e0 + 1) * 8 + u]);
    ull hp1 = pk(h0[(size_t)e1 * 8 + u], h0[(size_t)(e1 + 1) * 8 + u]);
    float c0l = c0[(size_t)e0 * 8 + u], c0h = c0[(size_t)(e0 + 1) * 8 + u];
    float c1l = c0[(size_t)e1 * 8 + u], c1h = c0[(size_t)(e1 + 1) * 8 + u];

    run_phase<T_OBS, 0>(hbuf[warp], &xbuf[warp][0][0], obs, P0, q, u,
                        hp0, hp1, c0l, c0h, c1l, c1h);
    // c_out = transpose(h_obs): out[u*B + b]
    *(ull*)(out + (size_t)u * NB + e0) = hp0;
    *(ull*)(out + (size_t)u * NB + e1) = hp1;

    c0l = c0p[(size_t)e0 * 8 + u]; c0h = c0p[(size_t)(e0 + 1) * 8 + u];  // cell re-init
    c1l = c0p[(size_t)e1 * 8 + u]; c1h = c0p[(size_t)(e1 + 1) * 8 + u];
    run_phase<T_PRE, 1>(hbuf[warp], &xbuf[warp][0][0], pre, P0, q, u,
                        hp0, hp1, c0l, c0h, c1l, c1h);
    float* out2 = out + (size_t)NB * 8;
    *(ull*)(out2 + (size_t)u * NB + e0) = hp0;
    *(ull*)(out2 + (size_t)u * NB + e1) = hp1;
}

extern "C" void kernel_launch(void* const* d_in, const int* in_sizes, int n_in,
                              void* d_out, int out_size)
{
    const float* obs   = (const float*)d_in[0];
    const float* pre   = (const float*)d_in[1];
    const float* h0    = (const float*)d_in[2];
    const float* c0    = (const float*)d_in[3];
    const float* c0p   = (const float*)d_in[4];
    const float* W_in  = (const float*)d_in[5];
    const float* b_in  = (const float*)d_in[6];
    const float* Wih_o = (const float*)d_in[7];
    const float* Whh_o = (const float*)d_in[8];
    const float* bih_o = (const float*)d_in[9];
    const float* bhh_o = (const float*)d_in[10];
    const float* Wih_p = (const float*)d_in[11];
    const float* Whh_p = (const float*)d_in[12];
    const float* bih_p = (const float*)d_in[13];
    const float* bhh_p = (const float*)d_in[14];

    prep_kernel<<<1, 64>>>(W_in, b_in, Wih_o, Whh_o, bih_o, bhh_o,
                           Wih_p, Whh_p, bih_p, bhh_p);
    // 1 warp = 16 elems, 4 warps/block -> 64 elems/block
    enc_kernel<<<NB / 64, 128>>>(obs, pre, h0, c0, c0p, (float*)d_out);
}

// round 17
// speedup vs baseline: 1.2383x; 1.0863x over previous
#include <cuda_runtime.h>

#define NB 524288
#define T_OBS 8
#define T_PRE 12
#define HH 8
#define EE 16

typedef unsigned long long ull;

// Duplicated (w,w) packed weights.
// Gates i,f,o pre-scaled by 0.5 (sigmoid(x)=0.5*tanh(x/2)+0.5); gate g unscaled.
struct __align__(16) Wpack {
    float2 W[2][8][8][4];   // [phase][u][k][gate]
    float2 A[2][8][2][4];   // [phase][u][m][gate]   (A = W_ih @ W_in, folded)
    float2 Bz[2][8][4];     // [phase][u][gate]      (b_ih + b_hh + W_ih@b_in, folded)
};
__device__ Wpack gPack;

// ---------------- prep: fold embedding into gate weights, scale, duplicate ----------------
__global__ void prep_kernel(
    const float* __restrict__ W_in, const float* __restrict__ b_in,
    const float* __restrict__ Wih_o, const float* __restrict__ Whh_o,
    const float* __restrict__ bih_o, const float* __restrict__ bhh_o,
    const float* __restrict__ Wih_p, const float* __restrict__ Whh_p,
    const float* __restrict__ bih_p, const float* __restrict__ bhh_p)
{
    int t = threadIdx.x;
    if (t >= 64) return;
    int ph = t >> 5, r = t & 31;
    const float* Wih = ph ? Wih_p : Wih_o;
    const float* Whh = ph ? Whh_p : Whh_o;
    const float* bih = ph ? bih_p : bih_o;
    const float* bhh = ph ? bhh_p : bhh_o;
    int g = r >> 3, j = r & 7;                       // rows: i(0-7) f(8-15) g(16-23) o(24-31)
    float sc = (g == 2) ? 1.0f : 0.5f;               // sigmoid via tanh(x/2); g: tanh direct
    float a0 = 0.f, a1 = 0.f, bb = bih[r] + bhh[r];
    for (int e = 0; e < EE; e++) {
        float w = Wih[r * EE + e];
        a0 += w * W_in[e * 2 + 0];
        a1 += w * W_in[e * 2 + 1];
        bb += w * b_in[e];
    }
    a0 *= sc; a1 *= sc; bb *= sc;
    gPack.A[ph][j][0][g] = make_float2(a0, a0);
    gPack.A[ph][j][1][g] = make_float2(a1, a1);
    gPack.Bz[ph][j][g]   = make_float2(bb, bb);
    for (int k = 0; k < HH; k++) {
        float w = Whh[r * HH + k] * sc;
        gPack.W[ph][j][k][g] = make_float2(w, w);
    }
}

// ---------------- packed f32x2 helpers ----------------
__device__ __forceinline__ ull fma2(ull a, ull b, ull c) {
    ull d; asm("fma.rn.f32x2 %0, %1, %2, %3;" : "=l"(d) : "l"(a), "l"(b), "l"(c)); return d;
}
__device__ __forceinline__ ull mul2(ull a, ull b) {
    ull d; asm("mul.rn.f32x2 %0, %1, %2;" : "=l"(d) : "l"(a), "l"(b)); return d;
}
__device__ __forceinline__ ull add2(ull a, ull b) {
    ull d; asm("add.rn.f32x2 %0, %1, %2;" : "=l"(d) : "l"(a), "l"(b)); return d;
}
__device__ __forceinline__ ull pk(float lo, float hi) {
    ull d; asm("mov.b64 %0, {%1, %2};" : "=l"(d) : "f"(lo), "f"(hi)); return d;
}
__device__ __forceinline__ void unpk(ull v, float& lo, float& hi) {
    asm("mov.b64 {%0, %1}, %2;" : "=f"(lo), "=f"(hi) : "l"(v));
}
__device__ __forceinline__ float tanhap(float x) {
    float y; asm("tanh.approx.f32 %0, %1;" : "=f"(y) : "f"(x)); return y;
}
__device__ __forceinline__ void cp16(unsigned dst, const void* src) {
    asm volatile("cp.async.cg.shared.global [%0], [%1], 16;" :: "r"(dst), "l"(src) : "memory");
}
__device__ __forceinline__ void cp_commit() {
    asm volatile("cp.async.commit_group;" ::: "memory");
}
__device__ __forceinline__ void cp_wait0() {
    asm volatile("cp.async.wait_group 0;" ::: "memory");
}

// LSTM epilogue, scalar per lane. acc = [i/2, f/2, g, o/2] preactivations (packed).
__device__ __forceinline__ void lstm_unit(const ull acc[4], float& cl, float& ch, ull& hout)
{
    float il, ih, fl, fh, gl, gh, ol, oh;
    unpk(acc[0], il, ih);
    unpk(acc[1], fl, fh);
    unpk(acc[2], gl, gh);
    unpk(acc[3], ol, oh);
    float til = tanhap(il), tih = tanhap(ih);
    float tfl = tanhap(fl), tfh = tanhap(fh);
    float tgl = tanhap(gl), tgh = tanhap(gh);
    float tol = tanhap(ol), toh = tanhap(oh);
    float sil = fmaf(til, 0.5f, 0.5f), sih = fmaf(tih, 0.5f, 0.5f);
    float sfl = fmaf(tfl, 0.5f, 0.5f), sfh = fmaf(tfh, 0.5f, 0.5f);
    float sol = fmaf(tol, 0.5f, 0.5f), soh = fmaf(toh, 0.5f, 0.5f);
    cl = fmaf(sfl, cl, sil * tgl);
    ch = fmaf(sfh, ch, sih * tgh);
    float tcl = tanhap(cl), tch = tanhap(ch);
    hout = pk(sol * tcl, soh * tch);
}

// Recurrent MAC for one pair: acc += W^T h, register weights; 2 tree halves
__device__ __forceinline__ void rec_mac(ull acc[4], const ull Wr[8][4], const ull* hv)
{
    ulonglong2 h01 = *(const ulonglong2*)(hv + 0);
    ulonglong2 h23 = *(const ulonglong2*)(hv + 2);
    ulonglong2 h45 = *(const ulonglong2*)(hv + 4);
    ulonglong2 h67 = *(const ulonglong2*)(hv + 6);
    #pragma unroll
    for (int g = 0; g < 4; g++) {
        ull a = fma2(Wr[0][g], h01.x, acc[g]);
        a = fma2(Wr[1][g], h01.y, a);
        a = fma2(Wr[2][g], h23.x, a);
        a = fma2(Wr[3][g], h23.y, a);
        ull b = mul2(Wr[4][g], h45.x);
        b = fma2(Wr[5][g], h45.y, b);
        b = fma2(Wr[6][g], h67.x, b);
        b = fma2(Wr[7][g], h67.y, b);
        acc[g] = add2(a, b);
    }
}

// h-exchange layout: pair stride = 10 ull (80B, 16B-aligned) -> conflict-free LDS.128.
#define HSTRIDE 10
#define HBUF    80      // ull per buffer (8 pair-slots x 10)
#define XSLOTS  12      // max TSTEPS

// hw: this warp's h-exchange region (2 bufs x HBUF ull)
// xs: this warp's x-staging region (XSLOTS slots x 8 pairs x float4)
template<int TSTEPS, int PH>
__device__ __forceinline__ void run_phase(ull* hw, float4* xs,
    const float* __restrict__ xbase, int P0, int q, int u,
    ull& hp0, ull& hp1,
    float& c0l, float& c0h, float& c1l, float& c1h)
{
    const float4* gx = (const float4*)xbase;   // x[t] for pair P: gx[t*S4 + P]
    const size_t S4 = (size_t)NB / 2;
    const unsigned xs_u32 = (unsigned)__cvta_generic_to_shared(xs);

    // lanes u==0 and u==4 each copy one pair's 16B per slot
    const bool cp_lane = (u & 3) == 0;
    const int cp_slot  = q + (u & 4);            // pair-slot this lane copies (0..7)
    const int cp_P     = P0 - q + cp_slot;       // global pair idx (P0-q = gw*8)

    __syncwarp();   // prior readers of xs (previous phase) are done

    // ---- burst-stage the ENTIRE phase's x: TSTEPS LDGSTS in flight at once ----
    if (cp_lane) {
        #pragma unroll
        for (int s = 0; s < TSTEPS; s++)
            cp16(xs_u32 + (unsigned)((s * 8 + cp_slot) * 16), gx + (size_t)s * S4 + cp_P);
    }
    cp_commit();

    // ---- phase-resident coefficients in registers (overlap with cp.async flight) ----
    ull Wr[8][4];
    #pragma unroll
    for (int k = 0; k < 8; k++) {
        const ulonglong2* ww = (const ulonglong2*)&gPack.W[PH][u][k][0];
        ulonglong2 q01 = __ldg(ww), q23 = __ldg(ww + 1);
        Wr[k][0] = q01.x; Wr[k][1] = q01.y; Wr[k][2] = q23.x; Wr[k][3] = q23.y;
    }
    ull A0[4], A1[4], Bz[4];
    {
        const ulonglong2* a0 = (const ulonglong2*)&gPack.A[PH][u][0][0];
        const ulonglong2* a1 = (const ulonglong2*)&gPack.A[PH][u][1][0];
        const ulonglong2* bz = (const ulonglong2*)&gPack.Bz[PH][u][0];
        ulonglong2 w01 = __ldg(a0), w23 = __ldg(a0 + 1);
        ulonglong2 v01 = __ldg(a1), v23 = __ldg(a1 + 1);
        ulonglong2 b01 = __ldg(bz), b23 = __ldg(bz + 1);
        A0[0] = w01.x; A0[1] = w01.y; A0[2] = w23.x; A0[3] = w23.y;
        A1[0] = v01.x; A1[1] = v01.y; A1[2] = v23.x; A1[3] = v23.y;
        Bz[0] = b01.x; Bz[1] = b01.y; Bz[2] = b23.x; Bz[3] = b23.y;
    }

    // publish initial h into buffer 0
    hw[q * HSTRIDE + u] = hp0;
    hw[(q + 4) * HSTRIDE + u] = hp1;

    cp_wait0();          // one wait for the whole phase's x (latency amortized, MLP=TSTEPS)
    __syncwarp();        // x + initial h visible to all lanes

    #pragma unroll 4
    for (int t = 0; t < TSTEPS; t++) {
        // pure smem/register loop body — no global dependencies
        float4 xA = xs[t * 8 + q];
        float4 xB = xs[t * 8 + q + 4];

        ull acc0[4], acc1[4];
        {
            ull px0 = pk(xA.x, xA.z), px1 = pk(xA.y, xA.w);
            ull py0 = pk(xB.x, xB.z), py1 = pk(xB.y, xB.w);
            #pragma unroll
            for (int g = 0; g < 4; g++) {
                acc0[g] = fma2(A0[g], px0, Bz[g]); acc0[g] = fma2(A1[g], px1, acc0[g]);
                acc1[g] = fma2(A0[g], py0, Bz[g]); acc1[g] = fma2(A1[g], py1, acc1[g]);
            }
        }

        const ull* hb = hw + (t & 1) * HBUF;
        rec_mac(acc0, Wr, hb + q * HSTRIDE);
        rec_mac(acc1, Wr, hb + (q + 4) * HSTRIDE);

        ull* hn = hw + ((t + 1) & 1) * HBUF;
        lstm_unit(acc0, c0l, c0h, hp0);
        if (t + 1 < TSTEPS) hn[q * HSTRIDE + u] = hp0;        // early STS pair 0
        lstm_unit(acc1, c1l, c1h, hp1);
        if (t + 1 < TSTEPS) hn[(q + 4) * HSTRIDE + u] = hp1;  // early STS pair 1

        if (t + 1 < TSTEPS) __syncwarp();   // h visible for next step
    }
}

__global__ void __launch_bounds__(128, 3)
enc_kernel(const float* __restrict__ obs, const float* __restrict__ pre,
           const float* __restrict__ h0, const float* __restrict__ c0,
           const float* __restrict__ c0p, float* __restrict__ out)
{
    __shared__ ull hbuf[4][2 * HBUF];          // per-warp: 2 bufs x 8 pairs x stride10
    __shared__ float4 xbuf[4][XSLOTS][8];      // per-warp: 12 slots x 8 pairs

    // warp = 8 pairs = 16 elements; lane = q*8 + u; lane handles pairs q and q+4
    const int lane = threadIdx.x & 31;
    const int warp = threadIdx.x >> 5;
    const int q = lane >> 3;                 // pair-slot (0..3)
    const int u = lane & 7;                  // hidden unit (0..7)
    const int gw = blockIdx.x * 4 + warp;    // global warp index
    const int P0 = gw * 8 + q;               // first pair
    const int P1 = P0 + 4;                   // second pair
    const int e0 = 2 * P0, e1 = 2 * P1;

    // initial state: [B,8] layout, stride 8
    ull hp0 = pk(h0[(size_t)e0 * 8 + u], h0[(size_t)(e0 + 1) * 8 + u]);
    ull hp1 = pk(h0[(size_t)e1 * 8 + u], h0[(size_t)(e1 + 1) * 8 + u]);
    float c0l = c0[(size_t)e0 * 8 + u], c0h = c0[(size_t)(e0 + 1) * 8 + u];
    float c1l = c0[(size_t)e1 * 8 + u], c1h = c0[(size_t)(e1 + 1) * 8 + u];

    run_phase<T_OBS, 0>(hbuf[warp], &xbuf[warp][0][0], obs, P0, q, u,
                        hp0, hp1, c0l, c0h, c1l, c1h);
    // c_out = transpose(h_obs): out[u*B + b]
    *(ull*)(out + (size_t)u * NB + e0) = hp0;
    *(ull*)(out + (size_t)u * NB + e1) = hp1;

    c0l = c0p[(size_t)e0 * 8 + u]; c0h = c0p[(size_t)(e0 + 1) * 8 + u];  // cell re-init
    c1l = c0p[(size_t)e1 * 8 + u]; c1h = c0p[(size_t)(e1 + 1) * 8 + u];
    run_phase<T_PRE, 1>(hbuf[warp], &xbuf[warp][0][0], pre, P0, q, u,
                        hp0, hp1, c0l, c0h, c1l, c1h);
    float* out2 = out + (size_t)NB * 8;
    *(ull*)(out2 + (size_t)u * NB + e0) = hp0;
    *(ull*)(out2 + (size_t)u * NB + e1) = hp1;
}

extern "C" void kernel_launch(void* const* d_in, const int* in_sizes, int n_in,
                              void* d_out, int out_size)
{
    const float* obs   = (const float*)d_in[0];
    const float* pre   = (const float*)d_in[1];
    const float* h0    = (const float*)d_in[2];
    const float* c0    = (const float*)d_in[3];
    const float* c0p   = (const float*)d_in[4];
    const float* W_in  = (const float*)d_in[5];
    const float* b_in  = (const float*)d_in[6];
    const float* Wih_o = (const float*)d_in[7];
    const float* Whh_o = (const float*)d_in[8];
    const float* bih_o = (const float*)d_in[9];
    const float* bhh_o = (const float*)d_in[10];
    const float* Wih_p = (const float*)d_in[11];
    const float* Whh_p = (const float*)d_in[12];
    const float* bih_p = (const float*)d_in[13];
    const float* bhh_p = (const float*)d_in[14];

    prep_kernel<<<1, 64>>>(W_in, b_in, Wih_o, Whh_o, bih_o, bhh_o,
                           Wih_p, Whh_p, bih_p, bhh_p);
    // 1 warp = 16 elems, 4 warps/block -> 64 elems/block
    enc_kernel<<<NB / 64, 128>>>(obs, pre, h0, c0, c0p, (float*)d_out);
}